// round 5
// baseline (speedup 1.0000x reference)
#include <cuda_runtime.h>

// CASSI forward, fused single kernel.
//
//   y2[b,i,k]    = sum_l x[b,l,i,k-2l] * phi[i,k-2l]   (0 <= k-2l < N)
//   out[b,l,i,j] = phi[i,j] * y2[b,i,2l+j]
//
// R5: latency-bound attack. __launch_bounds__(256,4) gives ptxas a 64-reg
// budget so it can front-batch LDGs (deep MLP). Hot path (t >= 54) runs the
// k0/k1 streams fully unpredicated across all 28 bands.

#define B_      8
#define L_      28
#define M_      512
#define N_      512
#define STRIDE_ 2
#define NOUT_   (N_ + STRIDE_ * (L_ - 1))   // 566
#define Y2S_    568
#define TPB     256

__global__ __launch_bounds__(TPB, 4) void cassi_fused_kernel(
    const float* __restrict__ x,
    const float* __restrict__ phi,
    float* __restrict__ out)
{
    __shared__ __align__(16) float phi_s[N_];
    __shared__ __align__(16) float y2_s[Y2S_];

    const int bm = blockIdx.x;           // (b, i)
    const int b  = bm / M_;
    const int i  = bm % M_;
    const int t  = threadIdx.x;

    // ---- phi row i -> smem (float4) ----
    {
        const float4* p4 = reinterpret_cast<const float4*>(phi + (size_t)i * N_);
        if (t < N_ / 4)
            reinterpret_cast<float4*>(phi_s)[t] = p4[t];
    }
    __syncthreads();

    const float* xb = x + (size_t)b * (L_ * M_ * N_) + (size_t)i * N_;
    const size_t band_stride = (size_t)M_ * N_;

    float acc0 = 0.f, acc1 = 0.f, acc2 = 0.f;

    if (t >= 2 * (L_ - 1)) {
        // ---- hot path (t >= 54): k0 = t and k1 = t+256 in-range for ALL l.
        //      56 unpredicated loads; ptxas free to batch deeply. ----
        const float* xr = xb;
        #pragma unroll
        for (int l = 0; l < L_; ++l) {
            const int n0 = t - STRIDE_ * l;          // >= 0, < 512
            const int n1 = t + TPB - STRIDE_ * l;    // in [256-54, 511]
            acc0 += __ldcs(xr + n0) * phi_s[n0];
            acc1 += __ldcs(xr + n1) * phi_s[n1];
            xr += band_stride;
        }
    } else {
        // ---- edge path (t < 54): predicated k0, full k1, tail stream k2. ----
        const float* xr = xb;
        #pragma unroll
        for (int l = 0; l < L_; ++l) {
            const int n1 = t + TPB - STRIDE_ * l;
            acc1 += __ldcs(xr + n1) * phi_s[n1];

            unsigned n0 = (unsigned)(t - STRIDE_ * l);
            if (n0 < N_) acc0 += __ldcs(xr + n0) * phi_s[n0];

            unsigned n2 = (unsigned)(t + 2 * TPB - STRIDE_ * l);
            if (n2 < N_) acc2 += __ldcs(xr + n2) * phi_s[n2];
            xr += band_stride;
        }
    }

    y2_s[t] = acc0;
    y2_s[t + TPB] = acc1;
    if (t + 2 * TPB < NOUT_) y2_s[t + 2 * TPB] = acc2;   // t < 54
    __syncthreads();

    // ---- epilogue: thread t -> output columns j = {2t, 2t+1};
    //      y2 word offset 2l+2t == float2 index (l+t): conflict-free LDS.64 ----
    const float2 phi_reg = reinterpret_cast<const float2*>(phi_s)[t];
    float* ob = out + (size_t)b * (L_ * M_ * N_) + (size_t)i * N_ + 2 * t;

    #pragma unroll
    for (int l = 0; l < L_; ++l) {
        float2 yv = reinterpret_cast<const float2*>(y2_s)[l + t];
        float2 r;
        r.x = phi_reg.x * yv.x;
        r.y = phi_reg.y * yv.y;
        __stcs(reinterpret_cast<float2*>(ob + (size_t)l * band_stride), r);
    }
}

extern "C" void kernel_launch(void* const* d_in, const int* in_sizes, int n_in,
                              void* d_out, int out_size)
{
    const float* x   = (const float*)d_in[0];
    const float* phi = (const float*)d_in[1];
    float* out       = (float*)d_out;

    cassi_fused_kernel<<<B_ * M_, TPB>>>(x, phi, out);
}

// round 6
// speedup vs baseline: 1.0095x; 1.0095x over previous
#include <cuda_runtime.h>

// CASSI forward, fused single kernel.
//
//   y2[b,i,k]    = sum_l x[b,l,i,k-2l] * phi[i,k-2l]   (0 <= k-2l < N)
//   out[b,l,i,j] = phi[i,j] * y2[b,i,2l+j]
//
// R5: latency-bound attack. __launch_bounds__(256,4) gives ptxas a 64-reg
// budget so it can front-batch LDGs (deep MLP). Hot path (t >= 54) runs the
// k0/k1 streams fully unpredicated across all 28 bands.

#define B_      8
#define L_      28
#define M_      512
#define N_      512
#define STRIDE_ 2
#define NOUT_   (N_ + STRIDE_ * (L_ - 1))   // 566
#define Y2S_    568
#define TPB     256

__global__ __launch_bounds__(TPB, 4) void cassi_fused_kernel(
    const float* __restrict__ x,
    const float* __restrict__ phi,
    float* __restrict__ out)
{
    __shared__ __align__(16) float phi_s[N_];
    __shared__ __align__(16) float y2_s[Y2S_];

    const int bm = blockIdx.x;           // (b, i)
    const int b  = bm / M_;
    const int i  = bm % M_;
    const int t  = threadIdx.x;

    // ---- phi row i -> smem (float4) ----
    {
        const float4* p4 = reinterpret_cast<const float4*>(phi + (size_t)i * N_);
        if (t < N_ / 4)
            reinterpret_cast<float4*>(phi_s)[t] = p4[t];
    }
    __syncthreads();

    const float* xb = x + (size_t)b * (L_ * M_ * N_) + (size_t)i * N_;
    const size_t band_stride = (size_t)M_ * N_;

    float acc0 = 0.f, acc1 = 0.f, acc2 = 0.f;

    if (t >= 2 * (L_ - 1)) {
        // ---- hot path (t >= 54): k0 = t and k1 = t+256 in-range for ALL l.
        //      56 unpredicated loads; ptxas free to batch deeply. ----
        const float* xr = xb;
        #pragma unroll
        for (int l = 0; l < L_; ++l) {
            const int n0 = t - STRIDE_ * l;          // >= 0, < 512
            const int n1 = t + TPB - STRIDE_ * l;    // in [256-54, 511]
            acc0 += __ldcs(xr + n0) * phi_s[n0];
            acc1 += __ldcs(xr + n1) * phi_s[n1];
            xr += band_stride;
        }
    } else {
        // ---- edge path (t < 54): predicated k0, full k1, tail stream k2. ----
        const float* xr = xb;
        #pragma unroll
        for (int l = 0; l < L_; ++l) {
            const int n1 = t + TPB - STRIDE_ * l;
            acc1 += __ldcs(xr + n1) * phi_s[n1];

            unsigned n0 = (unsigned)(t - STRIDE_ * l);
            if (n0 < N_) acc0 += __ldcs(xr + n0) * phi_s[n0];

            unsigned n2 = (unsigned)(t + 2 * TPB - STRIDE_ * l);
            if (n2 < N_) acc2 += __ldcs(xr + n2) * phi_s[n2];
            xr += band_stride;
        }
    }

    y2_s[t] = acc0;
    y2_s[t + TPB] = acc1;
    if (t + 2 * TPB < NOUT_) y2_s[t + 2 * TPB] = acc2;   // t < 54
    __syncthreads();

    // ---- epilogue: thread t -> output columns j = {2t, 2t+1};
    //      y2 word offset 2l+2t == float2 index (l+t): conflict-free LDS.64 ----
    const float2 phi_reg = reinterpret_cast<const float2*>(phi_s)[t];
    float* ob = out + (size_t)b * (L_ * M_ * N_) + (size_t)i * N_ + 2 * t;

    #pragma unroll
    for (int l = 0; l < L_; ++l) {
        float2 yv = reinterpret_cast<const float2*>(y2_s)[l + t];
        float2 r;
        r.x = phi_reg.x * yv.x;
        r.y = phi_reg.y * yv.y;
        __stcs(reinterpret_cast<float2*>(ob + (size_t)l * band_stride), r);
    }
}

extern "C" void kernel_launch(void* const* d_in, const int* in_sizes, int n_in,
                              void* d_out, int out_size)
{
    const float* x   = (const float*)d_in[0];
    const float* phi = (const float*)d_in[1];
    float* out       = (float*)d_out;

    cassi_fused_kernel<<<B_ * M_, TPB>>>(x, phi, out);
}